// round 16
// baseline (speedup 1.0000x reference)
#include <cuda_runtime.h>
#include <cuda_fp16.h>

// ---- static problem shape -------------------------------------------------
#define BATCH   8
#define HH      32
#define WWID    32
#define CDIM    768
#define NHEADS  12
#define HD      64
#define SEQ     1024
#define BHEADS  96
#define N_QKV   2304

// ---- scratch (device globals; allocation is forbidden) ---------------------
__device__ __align__(256) __half g_Q  [(size_t)BHEADS * SEQ * HD];   // pre-scaled 1/8
__device__ __align__(256) __half g_K  [(size_t)BHEADS * SEQ * HD];
__device__ __align__(256) __half g_Vt [(size_t)BHEADS * HD * SEQ];   // [bh][d][s]
__device__ __align__(256) float  g_RH [(size_t)BHEADS * SEQ * HH];
__device__ __align__(256) float  g_RW [(size_t)BHEADS * SEQ * WWID];
__device__ __align__(256) __half g_ATT[(size_t)BATCH * SEQ * CDIM];
__device__ __align__(256) __half g_W1t[(size_t)N_QKV * CDIM];        // [n][k]
__device__ __align__(256) __half g_W2t[(size_t)CDIM * CDIM];         // [n][k]

// ---- helpers ---------------------------------------------------------------
__device__ __forceinline__ unsigned pack_half2(float lo, float hi) {
    unsigned r;
    asm("cvt.rn.f16x2.f32 %0, %1, %2;" : "=r"(r) : "f"(hi), "f"(lo));
    return r;
}
__device__ __forceinline__ void mma_f16(float c[4], const unsigned a[4],
                                        const unsigned b0, const unsigned b1) {
    asm volatile(
        "mma.sync.aligned.m16n8k16.row.col.f32.f16.f16.f32 "
        "{%0,%1,%2,%3},{%4,%5,%6,%7},{%8,%9},{%0,%1,%2,%3};"
        : "+f"(c[0]), "+f"(c[1]), "+f"(c[2]), "+f"(c[3])
        : "r"(a[0]), "r"(a[1]), "r"(a[2]), "r"(a[3]), "r"(b0), "r"(b1));
}

// ===========================================================================
// Pre-pass: transpose + convert weights.  Wt[n][k] = fp16(W[k][n]).
// ===========================================================================
__global__ void __launch_bounds__(256) transpose_cvt_kernel(
    const float* __restrict__ W, __half* __restrict__ Wt, int K, int N)
{
    __shared__ float tile[32][33];
    const int n0 = blockIdx.x * 32, k0 = blockIdx.y * 32;
    const int tx = threadIdx.x & 31, ty = threadIdx.x >> 5;
#pragma unroll
    for (int r = 0; r < 32; r += 8)
        tile[ty + r][tx] = W[(size_t)(k0 + ty + r) * N + n0 + tx];
    __syncthreads();
#pragma unroll
    for (int r = 0; r < 32; r += 8)
        Wt[(size_t)(n0 + ty + r) * K + k0 + tx] = __float2half(tile[tx][ty + r]);
}

// ===========================================================================
// fp16 GEMM (round-12 structure): out = X @ W + bias, computed transposed
// (D = W^T @ X^T).  Block 128N x 128M, 8 warps (warp tile 32N x 64M),
// k-step 64, synchronous copies.  QKV variant reads X as fp32 and converts
// while staging (fuses the old cvt_kernel pass); proj variant reads fp16.
// ===========================================================================
template<bool QKV_SCATTER>
__global__ void __launch_bounds__(256, 2) gemm_f16_kernel(
    const void* __restrict__ Xv, const __half* __restrict__ Wt,
    const float* __restrict__ bias, float* __restrict__ out)
{
    __shared__ unsigned Wsm[128 * 36];
    __shared__ unsigned Xsm[128 * 36];

    const int t = threadIdx.x;
    const int w = t >> 5, lane = t & 31, g = lane >> 2, t4 = lane & 3;
    const int warpN = (w & 3) * 32, warpM = (w >> 2) * 64;
    const int bn = blockIdx.x * 128, bm = blockIdx.y * 128;

    float acc[2][8][4] = {};

    for (int i = 0; i < 12; i++) {
        uint4 wreg[4], xreg[4];
#pragma unroll
        for (int j = 0; j < 4; j++) {
            const int idx = t + 256 * j;
            const int row = idx >> 3, u4 = idx & 7;
            wreg[j] = *(const uint4*)(Wt + (size_t)(bn + row) * CDIM
                                      + i * 64 + u4 * 8);
            if (QKV_SCATTER) {
                // fp32 hidden: load 8 floats, convert to 8 halves
                const float* Xp = (const float*)Xv
                    + (size_t)(bm + row) * CDIM + i * 64 + u4 * 8;
                float4 a = *(const float4*)Xp;
                float4 b = *(const float4*)(Xp + 4);
                xreg[j] = make_uint4(pack_half2(a.x, a.y), pack_half2(a.z, a.w),
                                     pack_half2(b.x, b.y), pack_half2(b.z, b.w));
            } else {
                xreg[j] = *(const uint4*)((const __half*)Xv
                    + (size_t)(bm + row) * CDIM + i * 64 + u4 * 8);
            }
        }
        __syncthreads();
#pragma unroll
        for (int j = 0; j < 4; j++) {
            const int idx = t + 256 * j;
            const int row = idx >> 3, u4 = idx & 7;
            *(uint4*)&Wsm[row * 36 + u4 * 4] = wreg[j];
            *(uint4*)&Xsm[row * 36 + u4 * 4] = xreg[j];
        }
        __syncthreads();

#pragma unroll
        for (int ks = 0; ks < 4; ks++) {
            const int kw = ks * 8;
            unsigned a[2][4];
#pragma unroll
            for (int mt = 0; mt < 2; mt++) {
                const int nr = warpN + mt * 16 + g;
                a[mt][0] = Wsm[nr * 36 + kw + t4];
                a[mt][1] = Wsm[(nr + 8) * 36 + kw + t4];
                a[mt][2] = Wsm[nr * 36 + kw + t4 + 4];
                a[mt][3] = Wsm[(nr + 8) * 36 + kw + t4 + 4];
            }
#pragma unroll
            for (int nt = 0; nt < 8; nt++) {
                const int mr = (warpM + nt * 8 + g) * 36 + kw;
                const unsigned b0 = Xsm[mr + t4];
                const unsigned b1 = Xsm[mr + t4 + 4];
                mma_f16(acc[0][nt], a[0], b0, b1);
                mma_f16(acc[1][nt], a[1], b0, b1);
            }
        }
    }

#pragma unroll
    for (int mt = 0; mt < 2; mt++) {
#pragma unroll
        for (int nt = 0; nt < 8; nt++) {
            const int ncol0 = bn + warpN + mt * 16 + g;
            const int mrow  = bm + warpM + nt * 8 + 2 * t4;
#pragma unroll
            for (int h8 = 0; h8 < 2; h8++) {
                const int ncol = ncol0 + h8 * 8;
                const float bs = __ldg(bias + ncol);
                const float v0 = acc[mt][nt][h8 * 2 + 0] + bs;
                const float v1 = acc[mt][nt][h8 * 2 + 1] + bs;
                if (QKV_SCATTER) {
                    const int which = ncol / CDIM;
                    const int rem   = ncol - which * CDIM;
                    const int h = rem >> 6, d = rem & 63;
                    const int b_ = mrow >> 10, s_ = mrow & 1023;
                    const int bh = b_ * NHEADS + h;
                    if (which == 2) {
                        __half* vp = g_Vt + ((size_t)bh * HD + d) * SEQ + s_;
                        vp[0] = __float2half(v0);
                        vp[1] = __float2half(v1);
                    } else {
                        __half* dst = (which == 0) ? g_Q : g_K;
                        const float sc = (which == 0) ? 0.125f : 1.0f;
                        const size_t base =
                            ((size_t)bh * SEQ + s_) * HD + d;
                        dst[base]      = __float2half(v0 * sc);
                        dst[base + HD] = __float2half(v1 * sc);
                    }
                } else {
                    out[(size_t)mrow * CDIM + ncol]       = v0;
                    out[(size_t)(mrow + 1) * CDIM + ncol] = v1;
                }
            }
        }
    }
}

// ===========================================================================
// relative-position bias (Q fp16, pre-scaled 1/8 -> output x8).
// ===========================================================================
__global__ void __launch_bounds__(256) rel_kernel(
    const float* __restrict__ rph, const float* __restrict__ rpw)
{
    __shared__ float Qs[32 * 65];
    __shared__ float Hs[32 * 65];
    __shared__ float Wt[63 * 65];

    const int bh = blockIdx.y;
    const int qh = blockIdx.x;
    const int t  = threadIdx.x;

    const __half* Qg = g_Q + ((size_t)bh * SEQ + qh * 32) * HD;
#pragma unroll
    for (int i = t; i < 2048; i += 256) {
        const int r = i >> 6, d = i & 63;
        Qs[r * 65 + d] = __half2float(Qg[i]);
        Hs[r * 65 + d] = __ldg(rph + (qh + r) * 64 + d);
    }
    for (int i = t; i < 4032; i += 256) {
        const int r = i >> 6, d = i & 63;
        Wt[r * 65 + d] = __ldg(rpw + i);
    }
    __syncthreads();

    const int w = t >> 5, lane = t & 31;
    const float* Qr = Qs + lane * 65;
    float acc[8] = {};

    if (w < 4) {
        const int baserow = 31 - w * 8;
#pragma unroll
        for (int d = 0; d < 64; d++) {
            const float qv = Qr[d];
#pragma unroll
            for (int j = 0; j < 8; j++)
                acc[j] = fmaf(qv, Hs[(baserow - j) * 65 + d], acc[j]);
        }
        float* out = g_RH + ((size_t)bh * SEQ + qh * 32 + lane) * HH + w * 8;
        *(float4*)out       = make_float4(acc[0]*8.f, acc[1]*8.f, acc[2]*8.f, acc[3]*8.f);
        *(float4*)(out + 4) = make_float4(acc[4]*8.f, acc[5]*8.f, acc[6]*8.f, acc[7]*8.f);
    } else {
        const int baserow = lane + 31 - (w - 4) * 8;
#pragma unroll
        for (int d = 0; d < 64; d++) {
            const float qv = Qr[d];
#pragma unroll
            for (int j = 0; j < 8; j++)
                acc[j] = fmaf(qv, Wt[(baserow - j) * 65 + d], acc[j]);
        }
        float* out = g_RW + ((size_t)bh * SEQ + qh * 32 + lane) * WWID
                     + (w - 4) * 8;
        *(float4*)out       = make_float4(acc[0]*8.f, acc[1]*8.f, acc[2]*8.f, acc[3]*8.f);
        *(float4*)(out + 4) = make_float4(acc[4]*8.f, acc[5]*8.f, acc[6]*8.f, acc[7]*8.f);
    }
}

// ===========================================================================
// fp16 flash attention (round-12 champion, unchanged).  Block = 64 queries
// (4 warps x 16 rows), 64-key tiles, synchronous copies, 3 CTA/SM.
// rw bias index = key & 31 = (nt&3)*8 + 2*t4.
// ===========================================================================
__global__ void __launch_bounds__(128, 3) flash_f16_kernel()
{
    __shared__ unsigned Ks[64 * 36];
    __shared__ unsigned Vs[64 * 36];

    const int t = threadIdx.x, w = t >> 5, lane = t & 31;
    const int g = lane >> 2, t4 = lane & 3;
    const int bh = blockIdx.y;
    const int q0 = blockIdx.x * 64;
    const int qrow = w * 16;

    const __half* Kg  = g_K  + (size_t)bh * SEQ * HD;
    const __half* Vtg = g_Vt + (size_t)bh * HD * SEQ;

    // ---- stage Q tile into Ks, pull fragments ------------------------------
    {
        const __half* Qg = g_Q + ((size_t)bh * SEQ + q0) * HD;
#pragma unroll
        for (int j = 0; j < 4; j++) {
            const int idx = t + 128 * j;
            const int row = idx >> 3, u4 = idx & 7;
            *(uint4*)&Ks[row * 36 + u4 * 4] =
                *(const uint4*)(Qg + (size_t)row * HD + u4 * 8);
        }
        __syncthreads();
    }
    unsigned qa[4][4];
#pragma unroll
    for (int c = 0; c < 4; c++) {
        const int kw = c * 8;
        qa[c][0] = Ks[(qrow + g) * 36 + kw + t4];
        qa[c][1] = Ks[(qrow + g + 8) * 36 + kw + t4];
        qa[c][2] = Ks[(qrow + g) * 36 + kw + t4 + 4];
        qa[c][3] = Ks[(qrow + g + 8) * 36 + kw + t4 + 4];
    }
    __syncthreads();   // all Q frags read before tile 0 overwrites Ks

    // ---- rw bias (tile-invariant, 32-wide) into registers ------------------
    const float* RWg = g_RW + ((size_t)bh * SEQ + q0) * 32;
    float rwA[4][2], rwB[4][2];
#pragma unroll
    for (int nb = 0; nb < 4; nb++) {
        rwA[nb][0] = __ldg(RWg + (qrow + g) * 32 + nb * 8 + 2 * t4);
        rwA[nb][1] = __ldg(RWg + (qrow + g) * 32 + nb * 8 + 2 * t4 + 1);
        rwB[nb][0] = __ldg(RWg + (qrow + g + 8) * 32 + nb * 8 + 2 * t4);
        rwB[nb][1] = __ldg(RWg + (qrow + g + 8) * 32 + nb * 8 + 2 * t4 + 1);
    }
    const float* RHg = g_RH + ((size_t)bh * SEQ + q0) * 32;

    float o[8][4] = {};
    float l0 = 0.f, l1 = 0.f;

    for (int kt = 0; kt < 16; kt++) {
        uint4 kreg[4], vreg[4];
#pragma unroll
        for (int j = 0; j < 4; j++) {
            const int idx = t + 128 * j;
            const int row = idx >> 3, u4 = idx & 7;
            kreg[j] = *(const uint4*)(Kg + (size_t)(kt * 64 + row) * HD
                                      + u4 * 8);
            vreg[j] = *(const uint4*)(Vtg + (size_t)row * SEQ + kt * 64
                                      + u4 * 8);
        }
        __syncthreads();
#pragma unroll
        for (int j = 0; j < 4; j++) {
            const int idx = t + 128 * j;
            const int row = idx >> 3, u4 = idx & 7;
            *(uint4*)&Ks[row * 36 + u4 * 4] = kreg[j];
            *(uint4*)&Vs[row * 36 + u4 * 4] = vreg[j];
        }
        __syncthreads();

        // ---- S = Q @ K^T ----------------------------------------------------
        float sreg[8][4] = {};
#pragma unroll
        for (int c = 0; c < 4; c++) {
            const int kw = c * 8;
#pragma unroll
            for (int nt = 0; nt < 8; nt++) {
                const int kr = (nt * 8 + g) * 36 + kw;
                const unsigned b0 = Ks[kr + t4];
                const unsigned b1 = Ks[kr + t4 + 4];
                mma_f16(sreg[nt], qa[c], b0, b1);
            }
        }

        // ---- softmax -> packed P fragments ----------------------------------
        const float rhA0 = __ldg(RHg + (qrow + g) * 32 + kt * 2);
        const float rhA1 = __ldg(RHg + (qrow + g) * 32 + kt * 2 + 1);
        const float rhB0 = __ldg(RHg + (qrow + g + 8) * 32 + kt * 2);
        const float rhB1 = __ldg(RHg + (qrow + g + 8) * 32 + kt * 2 + 1);
        unsigned pk[8][2];
#pragma unroll
        for (int nt = 0; nt < 8; nt++) {
            const float bA = (nt < 4) ? rhA0 : rhA1;
            const float bB = (nt < 4) ? rhB0 : rhB1;
            const int n4 = nt & 3;   // key&31 = (nt&3)*8 + 2*t4
            const float p00 = __expf(fminf(sreg[nt][0] + bA + rwA[n4][0], 60.f));
            const float p01 = __expf(fminf(sreg[nt][1] + bA + rwA[n4][1], 60.f));
            const float p10 = __expf(fminf(sreg[nt][2] + bB + rwB[n4][0], 60.f));
            const float p11 = __expf(fminf(sreg[nt][3] + bB + rwB[n4][1], 60.f));
            l0 += p00 + p01;
            l1 += p10 + p11;
            pk[nt][0] = pack_half2(p00, p01);
            pk[nt][1] = pack_half2(p10, p11);
        }

        // ---- O += P @ V -----------------------------------------------------
#pragma unroll
        for (int kv = 0; kv < 4; kv++) {
            unsigned ap[4];
            ap[0] = pk[2 * kv][0];
            ap[1] = pk[2 * kv][1];
            ap[2] = pk[2 * kv + 1][0];
            ap[3] = pk[2 * kv + 1][1];
            const int kw = kv * 8;
#pragma unroll
            for (int db = 0; db < 8; db++) {
                const int vr = (db * 8 + g) * 36 + kw;
                const unsigned b0 = Vs[vr + t4];
                const unsigned b1 = Vs[vr + t4 + 4];
                mma_f16(o[db], ap, b0, b1);
            }
        }
    }

    // ---- finalize -----------------------------------------------------------
    l0 += __shfl_xor_sync(0xffffffffu, l0, 1);
    l0 += __shfl_xor_sync(0xffffffffu, l0, 2);
    l1 += __shfl_xor_sync(0xffffffffu, l1, 1);
    l1 += __shfl_xor_sync(0xffffffffu, l1, 2);
    const float inv0 = 1.f / l0;
    const float inv1 = 1.f / l1;

    const int b_ = bh / NHEADS, h = bh - b_ * NHEADS;
    const int rowA = q0 + qrow + g, rowB = rowA + 8;
    __half* OgA = g_ATT + ((size_t)b_ * SEQ + rowA) * CDIM + h * HD;
    __half* OgB = g_ATT + ((size_t)b_ * SEQ + rowB) * CDIM + h * HD;
#pragma unroll
    for (int db = 0; db < 8; db++) {
        const int c = db * 8 + 2 * t4;
        OgA[c]     = __float2half(o[db][0] * inv0);
        OgA[c + 1] = __float2half(o[db][1] * inv0);
        OgB[c]     = __float2half(o[db][2] * inv1);
        OgB[c + 1] = __float2half(o[db][3] * inv1);
    }
}

// ===========================================================================
// launch
// ===========================================================================
extern "C" void kernel_launch(void* const* d_in, const int* in_sizes, int n_in,
                              void* d_out, int out_size)
{
    const float* hidden = (const float*)d_in[0];
    const float* qkv_w  = (const float*)d_in[1];
    const float* qkv_b  = (const float*)d_in[2];
    const float* proj_w = (const float*)d_in[3];
    const float* proj_b = (const float*)d_in[4];
    const float* rph    = (const float*)d_in[5];
    const float* rpw    = (const float*)d_in[6];
    float* out = (float*)d_out;

    __half *w1t_ptr = nullptr, *w2t_ptr = nullptr, *att_ptr = nullptr;
    cudaGetSymbolAddress((void**)&w1t_ptr, g_W1t);
    cudaGetSymbolAddress((void**)&w2t_ptr, g_W2t);
    cudaGetSymbolAddress((void**)&att_ptr, g_ATT);

    // transpose+convert weights (hidden is converted inside the qkv GEMM)
    transpose_cvt_kernel<<<dim3(N_QKV / 32, CDIM / 32), 256>>>(
        qkv_w, w1t_ptr, CDIM, N_QKV);
    transpose_cvt_kernel<<<dim3(CDIM / 32, CDIM / 32), 256>>>(
        proj_w, w2t_ptr, CDIM, CDIM);

    gemm_f16_kernel<true>
        <<<dim3(N_QKV / 128, (BATCH * SEQ) / 128), 256>>>(
            hidden, w1t_ptr, qkv_b, nullptr);
    rel_kernel<<<dim3(HH, BHEADS), 256>>>(rph, rpw);
    flash_f16_kernel<<<dim3(SEQ / 64, BHEADS), 128>>>();
    gemm_f16_kernel<false>
        <<<dim3(CDIM / 128, (BATCH * SEQ) / 128), 256>>>(
            att_ptr, w2t_ptr, proj_b, out);
}

// round 17
// speedup vs baseline: 1.2116x; 1.2116x over previous
#include <cuda_runtime.h>
#include <cuda_fp16.h>

// ---- static problem shape -------------------------------------------------
#define BATCH   8
#define HH      32
#define WWID    32
#define CDIM    768
#define NHEADS  12
#define HD      64
#define SEQ     1024
#define BHEADS  96
#define N_QKV   2304

// ---- scratch (device globals; allocation is forbidden) ---------------------
__device__ __align__(256) __half g_Q  [(size_t)BHEADS * SEQ * HD];   // pre-scaled 1/8
__device__ __align__(256) __half g_K  [(size_t)BHEADS * SEQ * HD];
__device__ __align__(256) __half g_Vt [(size_t)BHEADS * HD * SEQ];   // [bh][d][s]
__device__ __align__(256) float  g_RH [(size_t)BHEADS * SEQ * HH];
__device__ __align__(256) float  g_RW [(size_t)BHEADS * SEQ * WWID];
__device__ __align__(256) __half g_ATT[(size_t)BATCH * SEQ * CDIM];
__device__ __align__(256) __half g_X  [(size_t)BATCH * SEQ * CDIM];
__device__ __align__(256) __half g_W1t[(size_t)N_QKV * CDIM];        // [n][k]
__device__ __align__(256) __half g_W2t[(size_t)CDIM * CDIM];         // [n][k]

// ---- helpers ---------------------------------------------------------------
__device__ __forceinline__ unsigned pack_half2(float lo, float hi) {
    unsigned r;
    asm("cvt.rn.f16x2.f32 %0, %1, %2;" : "=r"(r) : "f"(hi), "f"(lo));
    return r;
}
__device__ __forceinline__ void mma_f16(float c[4], const unsigned a[4],
                                        const unsigned b0, const unsigned b1) {
    asm volatile(
        "mma.sync.aligned.m16n8k16.row.col.f32.f16.f16.f32 "
        "{%0,%1,%2,%3},{%4,%5,%6,%7},{%8,%9},{%0,%1,%2,%3};"
        : "+f"(c[0]), "+f"(c[1]), "+f"(c[2]), "+f"(c[3])
        : "r"(a[0]), "r"(a[1]), "r"(a[2]), "r"(a[3]), "r"(b0), "r"(b1));
}

// ===========================================================================
// Pre-pass 1: fp32 -> fp16 elementwise (hidden).
// ===========================================================================
__global__ void __launch_bounds__(256) cvt_kernel(
    const float4* __restrict__ src, uint2* __restrict__ dst, int n4)
{
    const int i = blockIdx.x * 256 + threadIdx.x;
    if (i < n4) {
        float4 v = src[i];
        dst[i] = make_uint2(pack_half2(v.x, v.y), pack_half2(v.z, v.w));
    }
}

// ===========================================================================
// Pre-pass 2: transpose + convert weights.  Wt[n][k] = fp16(W[k][n]).
// ===========================================================================
__global__ void __launch_bounds__(256) transpose_cvt_kernel(
    const float* __restrict__ W, __half* __restrict__ Wt, int K, int N)
{
    __shared__ float tile[32][33];
    const int n0 = blockIdx.x * 32, k0 = blockIdx.y * 32;
    const int tx = threadIdx.x & 31, ty = threadIdx.x >> 5;
#pragma unroll
    for (int r = 0; r < 32; r += 8)
        tile[ty + r][tx] = W[(size_t)(k0 + ty + r) * N + n0 + tx];
    __syncthreads();
#pragma unroll
    for (int r = 0; r < 32; r += 8)
        Wt[(size_t)(n0 + ty + r) * K + k0 + tx] = __float2half(tile[tx][ty + r]);
}

// ===========================================================================
// fp16 GEMM (round-12 champion): out = X @ W + bias, computed transposed.
// Block 128N x 128M, 8 warps (32N x 64M each), k-step 64, sync copies.
// ===========================================================================
template<bool QKV_SCATTER>
__global__ void __launch_bounds__(256, 2) gemm_f16_kernel(
    const __half* __restrict__ X, const __half* __restrict__ Wt,
    const float* __restrict__ bias, float* __restrict__ out)
{
    __shared__ unsigned Wsm[128 * 36];
    __shared__ unsigned Xsm[128 * 36];

    const int t = threadIdx.x;
    const int w = t >> 5, lane = t & 31, g = lane >> 2, t4 = lane & 3;
    const int warpN = (w & 3) * 32, warpM = (w >> 2) * 64;
    const int bn = blockIdx.x * 128, bm = blockIdx.y * 128;

    float acc[2][8][4] = {};

    for (int i = 0; i < 12; i++) {
        uint4 wreg[4], xreg[4];
#pragma unroll
        for (int j = 0; j < 4; j++) {
            const int idx = t + 256 * j;
            const int row = idx >> 3, u4 = idx & 7;
            wreg[j] = *(const uint4*)(Wt + (size_t)(bn + row) * CDIM
                                      + i * 64 + u4 * 8);
            xreg[j] = *(const uint4*)(X + (size_t)(bm + row) * CDIM
                                      + i * 64 + u4 * 8);
        }
        __syncthreads();
#pragma unroll
        for (int j = 0; j < 4; j++) {
            const int idx = t + 256 * j;
            const int row = idx >> 3, u4 = idx & 7;
            *(uint4*)&Wsm[row * 36 + u4 * 4] = wreg[j];
            *(uint4*)&Xsm[row * 36 + u4 * 4] = xreg[j];
        }
        __syncthreads();

#pragma unroll
        for (int ks = 0; ks < 4; ks++) {
            const int kw = ks * 8;
            unsigned a[2][4];
#pragma unroll
            for (int mt = 0; mt < 2; mt++) {
                const int nr = warpN + mt * 16 + g;
                a[mt][0] = Wsm[nr * 36 + kw + t4];
                a[mt][1] = Wsm[(nr + 8) * 36 + kw + t4];
                a[mt][2] = Wsm[nr * 36 + kw + t4 + 4];
                a[mt][3] = Wsm[(nr + 8) * 36 + kw + t4 + 4];
            }
#pragma unroll
            for (int nt = 0; nt < 8; nt++) {
                const int mr = (warpM + nt * 8 + g) * 36 + kw;
                const unsigned b0 = Xsm[mr + t4];
                const unsigned b1 = Xsm[mr + t4 + 4];
                mma_f16(acc[0][nt], a[0], b0, b1);
                mma_f16(acc[1][nt], a[1], b0, b1);
            }
        }
    }

#pragma unroll
    for (int mt = 0; mt < 2; mt++) {
#pragma unroll
        for (int nt = 0; nt < 8; nt++) {
            const int ncol0 = bn + warpN + mt * 16 + g;
            const int mrow  = bm + warpM + nt * 8 + 2 * t4;
#pragma unroll
            for (int h8 = 0; h8 < 2; h8++) {
                const int ncol = ncol0 + h8 * 8;
                const float bs = __ldg(bias + ncol);
                const float v0 = acc[mt][nt][h8 * 2 + 0] + bs;
                const float v1 = acc[mt][nt][h8 * 2 + 1] + bs;
                if (QKV_SCATTER) {
                    const int which = ncol / CDIM;
                    const int rem   = ncol - which * CDIM;
                    const int h = rem >> 6, d = rem & 63;
                    const int b_ = mrow >> 10, s_ = mrow & 1023;
                    const int bh = b_ * NHEADS + h;
                    if (which == 2) {
                        __half* vp = g_Vt + ((size_t)bh * HD + d) * SEQ + s_;
                        vp[0] = __float2half(v0);
                        vp[1] = __float2half(v1);
                    } else {
                        __half* dst = (which == 0) ? g_Q : g_K;
                        const float sc = (which == 0) ? 0.125f : 1.0f;
                        const size_t base =
                            ((size_t)bh * SEQ + s_) * HD + d;
                        dst[base]      = __float2half(v0 * sc);
                        dst[base + HD] = __float2half(v1 * sc);
                    }
                } else {
                    out[(size_t)mrow * CDIM + ncol]       = v0;
                    out[(size_t)(mrow + 1) * CDIM + ncol] = v1;
                }
            }
        }
    }
}

// ===========================================================================
// relative-position bias via tensor cores.  One block per (bh, qh).
//   RH[q',kh] = Q[q'] . rph[qh+31-kh]          (32x32x64 GEMM, warps 0-1)
//   tmp[q',r] = Q[q'] . rpw[r], r=0..62        (32x64x64 GEMM, warps 2-5)
//   RW[q',kw] = tmp[q', q'+31-kw]              (Toeplitz gather, all warps)
// Q is fp16 pre-scaled 1/8 -> results x8.
// ===========================================================================
__global__ void __launch_bounds__(256) rel_kernel(
    const float* __restrict__ rph, const float* __restrict__ rpw)
{
    __shared__ unsigned Qs[32 * 36];
    __shared__ unsigned Hs[32 * 36];
    __shared__ unsigned Ws[64 * 36];
    __shared__ float    tmp[32 * 68];

    const int bh = blockIdx.y;
    const int qh = blockIdx.x;
    const int t  = threadIdx.x;
    const int w = t >> 5, lane = t & 31, g = lane >> 2, t4 = lane & 3;

    // ---- stage Q (fp16, 32x64) -------------------------------------------
    {
        const __half* Qg = g_Q + ((size_t)bh * SEQ + qh * 32) * HD;
        const int row = t >> 3, u4 = t & 7;   // 32 rows x 8 uint4
        *(uint4*)&Qs[row * 36 + u4 * 4] =
            *(const uint4*)(Qg + (size_t)row * HD + u4 * 8);
    }
    // ---- stage Hs[kh] = fp16(rph[qh+31-kh]) --------------------------------
    {
        const int row = t >> 3, seg = t & 7;   // 8 floats per thread
        const float* src = rph + (size_t)(qh + 31 - row) * 64 + seg * 8;
        float4 a = *(const float4*)src;
        float4 b = *(const float4*)(src + 4);
        *(uint4*)&Hs[row * 36 + seg * 4] =
            make_uint4(pack_half2(a.x, a.y), pack_half2(a.z, a.w),
                       pack_half2(b.x, b.y), pack_half2(b.z, b.w));
    }
    // ---- stage Ws[r] = fp16(rpw[r]), r<63; row 63 zero ----------------------
#pragma unroll
    for (int j = 0; j < 2; j++) {
        const int i = t + 256 * j;
        const int row = i >> 3, seg = i & 7;
        uint4 v;
        if (row < 63) {
            const float* src = rpw + (size_t)row * 64 + seg * 8;
            float4 a = *(const float4*)src;
            float4 b = *(const float4*)(src + 4);
            v = make_uint4(pack_half2(a.x, a.y), pack_half2(a.z, a.w),
                           pack_half2(b.x, b.y), pack_half2(b.z, b.w));
        } else {
            v = make_uint4(0, 0, 0, 0);
        }
        *(uint4*)&Ws[row * 36 + seg * 4] = v;
    }
    __syncthreads();

    if (w < 2) {
        // ---- RH: warp w handles q rows w*16..w*16+15 ------------------------
        const int qrow = w * 16;
        float acc[4][4] = {};
#pragma unroll
        for (int c = 0; c < 4; c++) {
            const int kw = c * 8;
            unsigned a[4];
            a[0] = Qs[(qrow + g) * 36 + kw + t4];
            a[1] = Qs[(qrow + g + 8) * 36 + kw + t4];
            a[2] = Qs[(qrow + g) * 36 + kw + t4 + 4];
            a[3] = Qs[(qrow + g + 8) * 36 + kw + t4 + 4];
#pragma unroll
            for (int nt = 0; nt < 4; nt++) {
                const int br = (nt * 8 + g) * 36 + kw;
                mma_f16(acc[nt], a, Hs[br + t4], Hs[br + t4 + 4]);
            }
        }
        float* base = g_RH + ((size_t)bh * SEQ + qh * 32) * HH;
#pragma unroll
        for (int nt = 0; nt < 4; nt++) {
            const int kh = nt * 8 + 2 * t4;
            float* r0 = base + (size_t)(qrow + g) * HH + kh;
            float* r1 = base + (size_t)(qrow + g + 8) * HH + kh;
            r0[0] = acc[nt][0] * 8.f;  r0[1] = acc[nt][1] * 8.f;
            r1[0] = acc[nt][2] * 8.f;  r1[1] = acc[nt][3] * 8.f;
        }
    } else if (w < 6) {
        // ---- tmp: warp (w-2) -> m-tile (0/1), n-half (0/1) ------------------
        const int wv = w - 2;
        const int qrow = (wv >> 1) * 16;
        const int nc0  = (wv & 1) * 32;
        float acc[4][4] = {};
#pragma unroll
        for (int c = 0; c < 4; c++) {
            const int kw = c * 8;
            unsigned a[4];
            a[0] = Qs[(qrow + g) * 36 + kw + t4];
            a[1] = Qs[(qrow + g + 8) * 36 + kw + t4];
            a[2] = Qs[(qrow + g) * 36 + kw + t4 + 4];
            a[3] = Qs[(qrow + g + 8) * 36 + kw + t4 + 4];
#pragma unroll
            for (int nt = 0; nt < 4; nt++) {
                const int br = (nc0 + nt * 8 + g) * 36 + kw;
                mma_f16(acc[nt], a, Ws[br + t4], Ws[br + t4 + 4]);
            }
        }
#pragma unroll
        for (int nt = 0; nt < 4; nt++) {
            const int col = nc0 + nt * 8 + 2 * t4;
            tmp[(qrow + g) * 68 + col]         = acc[nt][0];
            tmp[(qrow + g) * 68 + col + 1]     = acc[nt][1];
            tmp[(qrow + g + 8) * 68 + col]     = acc[nt][2];
            tmp[(qrow + g + 8) * 68 + col + 1] = acc[nt][3];
        }
    }
    __syncthreads();

    // ---- Toeplitz gather: RW[q',kw] = tmp[q', q'+31-kw] * 8 -----------------
    float* rwbase = g_RW + ((size_t)bh * SEQ + qh * 32) * WWID;
#pragma unroll
    for (int j = 0; j < 4; j++) {
        const int idx = t + 256 * j;
        const int qp = idx >> 5, kw = idx & 31;
        rwbase[(size_t)qp * WWID + kw] = tmp[qp * 68 + qp + 31 - kw] * 8.f;
    }
}

// ===========================================================================
// fp16 flash attention (round-12 champion, unchanged).
// ===========================================================================
__global__ void __launch_bounds__(128, 3) flash_f16_kernel()
{
    __shared__ unsigned Ks[64 * 36];
    __shared__ unsigned Vs[64 * 36];

    const int t = threadIdx.x, w = t >> 5, lane = t & 31;
    const int g = lane >> 2, t4 = lane & 3;
    const int bh = blockIdx.y;
    const int q0 = blockIdx.x * 64;
    const int qrow = w * 16;

    const __half* Kg  = g_K  + (size_t)bh * SEQ * HD;
    const __half* Vtg = g_Vt + (size_t)bh * HD * SEQ;

    {
        const __half* Qg = g_Q + ((size_t)bh * SEQ + q0) * HD;
#pragma unroll
        for (int j = 0; j < 4; j++) {
            const int idx = t + 128 * j;
            const int row = idx >> 3, u4 = idx & 7;
            *(uint4*)&Ks[row * 36 + u4 * 4] =
                *(const uint4*)(Qg + (size_t)row * HD + u4 * 8);
        }
        __syncthreads();
    }
    unsigned qa[4][4];
#pragma unroll
    for (int c = 0; c < 4; c++) {
        const int kw = c * 8;
        qa[c][0] = Ks[(qrow + g) * 36 + kw + t4];
        qa[c][1] = Ks[(qrow + g + 8) * 36 + kw + t4];
        qa[c][2] = Ks[(qrow + g) * 36 + kw + t4 + 4];
        qa[c][3] = Ks[(qrow + g + 8) * 36 + kw + t4 + 4];
    }
    __syncthreads();

    const float* RWg = g_RW + ((size_t)bh * SEQ + q0) * 32;
    float rwA[4][2], rwB[4][2];
#pragma unroll
    for (int nb = 0; nb < 4; nb++) {
        rwA[nb][0] = __ldg(RWg + (qrow + g) * 32 + nb * 8 + 2 * t4);
        rwA[nb][1] = __ldg(RWg + (qrow + g) * 32 + nb * 8 + 2 * t4 + 1);
        rwB[nb][0] = __ldg(RWg + (qrow + g + 8) * 32 + nb * 8 + 2 * t4);
        rwB[nb][1] = __ldg(RWg + (qrow + g + 8) * 32 + nb * 8 + 2 * t4 + 1);
    }
    const float* RHg = g_RH + ((size_t)bh * SEQ + q0) * 32;

    float o[8][4] = {};
    float l0 = 0.f, l1 = 0.f;

    for (int kt = 0; kt < 16; kt++) {
        uint4 kreg[4], vreg[4];
#pragma unroll
        for (int j = 0; j < 4; j++) {
            const int idx = t + 128 * j;
            const int row = idx >> 3, u4 = idx & 7;
            kreg[j] = *(const uint4*)(Kg + (size_t)(kt * 64 + row) * HD
                                      + u4 * 8);
            vreg[j] = *(const uint4*)(Vtg + (size_t)row * SEQ + kt * 64
                                      + u4 * 8);
        }
        __syncthreads();
#pragma unroll
        for (int j = 0; j < 4; j++) {
            const int idx = t + 128 * j;
            const int row = idx >> 3, u4 = idx & 7;
            *(uint4*)&Ks[row * 36 + u4 * 4] = kreg[j];
            *(uint4*)&Vs[row * 36 + u4 * 4] = vreg[j];
        }
        __syncthreads();

        float sreg[8][4] = {};
#pragma unroll
        for (int c = 0; c < 4; c++) {
            const int kw = c * 8;
#pragma unroll
            for (int nt = 0; nt < 8; nt++) {
                const int kr = (nt * 8 + g) * 36 + kw;
                const unsigned b0 = Ks[kr + t4];
                const unsigned b1 = Ks[kr + t4 + 4];
                mma_f16(sreg[nt], qa[c], b0, b1);
            }
        }

        const float rhA0 = __ldg(RHg + (qrow + g) * 32 + kt * 2);
        const float rhA1 = __ldg(RHg + (qrow + g) * 32 + kt * 2 + 1);
        const float rhB0 = __ldg(RHg + (qrow + g + 8) * 32 + kt * 2);
        const float rhB1 = __ldg(RHg + (qrow + g + 8) * 32 + kt * 2 + 1);
        unsigned pk[8][2];
#pragma unroll
        for (int nt = 0; nt < 8; nt++) {
            const float bA = (nt < 4) ? rhA0 : rhA1;
            const float bB = (nt < 4) ? rhB0 : rhB1;
            const int n4 = nt & 3;
            const float p00 = __expf(fminf(sreg[nt][0] + bA + rwA[n4][0], 60.f));
            const float p01 = __expf(fminf(sreg[nt][1] + bA + rwA[n4][1], 60.f));
            const float p10 = __expf(fminf(sreg[nt][2] + bB + rwB[n4][0], 60.f));
            const float p11 = __expf(fminf(sreg[nt][3] + bB + rwB[n4][1], 60.f));
            l0 += p00 + p01;
            l1 += p10 + p11;
            pk[nt][0] = pack_half2(p00, p01);
            pk[nt][1] = pack_half2(p10, p11);
        }

#pragma unroll
        for (int kv = 0; kv < 4; kv++) {
            unsigned ap[4];
            ap[0] = pk[2 * kv][0];
            ap[1] = pk[2 * kv][1];
            ap[2] = pk[2 * kv + 1][0];
            ap[3] = pk[2 * kv + 1][1];
            const int kw = kv * 8;
#pragma unroll
            for (int db = 0; db < 8; db++) {
                const int vr = (db * 8 + g) * 36 + kw;
                const unsigned b0 = Vs[vr + t4];
                const unsigned b1 = Vs[vr + t4 + 4];
                mma_f16(o[db], ap, b0, b1);
            }
        }
    }

    l0 += __shfl_xor_sync(0xffffffffu, l0, 1);
    l0 += __shfl_xor_sync(0xffffffffu, l0, 2);
    l1 += __shfl_xor_sync(0xffffffffu, l1, 1);
    l1 += __shfl_xor_sync(0xffffffffu, l1, 2);
    const float inv0 = 1.f / l0;
    const float inv1 = 1.f / l1;

    const int b_ = bh / NHEADS, h = bh - b_ * NHEADS;
    const int rowA = q0 + qrow + g, rowB = rowA + 8;
    __half* OgA = g_ATT + ((size_t)b_ * SEQ + rowA) * CDIM + h * HD;
    __half* OgB = g_ATT + ((size_t)b_ * SEQ + rowB) * CDIM + h * HD;
#pragma unroll
    for (int db = 0; db < 8; db++) {
        const int c = db * 8 + 2 * t4;
        OgA[c]     = __float2half(o[db][0] * inv0);
        OgA[c + 1] = __float2half(o[db][1] * inv0);
        OgB[c]     = __float2half(o[db][2] * inv1);
        OgB[c + 1] = __float2half(o[db][3] * inv1);
    }
}

// ===========================================================================
// launch
// ===========================================================================
extern "C" void kernel_launch(void* const* d_in, const int* in_sizes, int n_in,
                              void* d_out, int out_size)
{
    const float* hidden = (const float*)d_in[0];
    const float* qkv_w  = (const float*)d_in[1];
    const float* qkv_b  = (const float*)d_in[2];
    const float* proj_w = (const float*)d_in[3];
    const float* proj_b = (const float*)d_in[4];
    const float* rph    = (const float*)d_in[5];
    const float* rpw    = (const float*)d_in[6];
    float* out = (float*)d_out;

    __half *x_ptr = nullptr, *w1t_ptr = nullptr, *w2t_ptr = nullptr,
           *att_ptr = nullptr;
    cudaGetSymbolAddress((void**)&x_ptr,   g_X);
    cudaGetSymbolAddress((void**)&w1t_ptr, g_W1t);
    cudaGetSymbolAddress((void**)&w2t_ptr, g_W2t);
    cudaGetSymbolAddress((void**)&att_ptr, g_ATT);

    // pre-convert hidden; transpose+convert weights
    {
        const int nX = BATCH * SEQ * CDIM / 4;
        cvt_kernel<<<(nX + 255) / 256, 256>>>((const float4*)hidden,
                                              (uint2*)x_ptr, nX);
        transpose_cvt_kernel<<<dim3(N_QKV / 32, CDIM / 32), 256>>>(
            qkv_w, w1t_ptr, CDIM, N_QKV);
        transpose_cvt_kernel<<<dim3(CDIM / 32, CDIM / 32), 256>>>(
            proj_w, w2t_ptr, CDIM, CDIM);
    }

    gemm_f16_kernel<true>
        <<<dim3(N_QKV / 128, (BATCH * SEQ) / 128), 256>>>(
            x_ptr, w1t_ptr, qkv_b, nullptr);
    rel_kernel<<<dim3(HH, BHEADS), 256>>>(rph, rpw);
    flash_f16_kernel<<<dim3(SEQ / 64, BHEADS), 128>>>();
    gemm_f16_kernel<false>
        <<<dim3(CDIM / 128, (BATCH * SEQ) / 128), 256>>>(
            att_ptr, w2t_ptr, proj_b, out);
}